// round 10
// baseline (speedup 1.0000x reference)
#include <cuda_runtime.h>
#include <cuda_bf16.h>
#include <cstdint>
#include <math.h>

#define HH 128
#define GG 512
#define MAXN 50000
#define NHH (MAXN * HH)

// ---------------- device scratch ----------------
__device__ float g_xh[NHH];
__device__ float g_agg1[NHH];
__device__ float g_agg2[NHH];
__device__ float g_c[NHH];
__device__ float g_ha[NHH];
__device__ float g_hb[NHH];
__device__ float g_on[NHH];
__device__ float g_gsum[GG * HH];
__device__ float g_gsq[GG * HH];
__device__ float g_gcnt[GG];
__device__ uint2 g_w12a[128 * 84];       // packed split-bf16 W12 (feature1)
__device__ uint2 g_w12b[128 * 20];       // (feature2)
__device__ uint2 g_wpk[13 * 128 * 68];   // packed node weights

// ---------------- bf16 split helpers ----------------
__device__ __forceinline__ uint2 splitbf2p(float2 v) {
    __nv_bfloat162 h = __float22bfloat162_rn(v);
    float2 hv = __bfloat1622float2(h);
    __nv_bfloat162 l = __float22bfloat162_rn(make_float2(v.x - hv.x, v.y - hv.y));
    uint2 r;
    r.x = *reinterpret_cast<uint32_t*>(&h);
    r.y = *reinterpret_cast<uint32_t*>(&l);
    return r;
}

__device__ __forceinline__ void mma16(float* d, uint32_t a0, uint32_t a1, uint32_t a2,
                                      uint32_t a3, uint32_t b0, uint32_t b1) {
    asm volatile(
        "mma.sync.aligned.m16n8k16.row.col.f32.bf16.bf16.f32 "
        "{%0,%1,%2,%3}, {%4,%5,%6,%7}, {%8,%9}, {%0,%1,%2,%3};\n"
        : "+f"(d[0]), "+f"(d[1]), "+f"(d[2]), "+f"(d[3])
        : "r"(a0), "r"(a1), "r"(a2), "r"(a3), "r"(b0), "r"(b1));
}

__device__ __forceinline__ void mma3(float* d, const uint2& a0, const uint2& a1,
                                     const uint2& a2, const uint2& a3,
                                     uint32_t bh0, uint32_t bh1, uint32_t bl0, uint32_t bl1) {
    mma16(d, a0.x, a1.x, a2.x, a3.x, bh0, bh1);
    mma16(d, a0.x, a1.x, a2.x, a3.x, bl0, bl1);
    mma16(d, a0.y, a1.y, a2.y, a3.y, bh0, bh1);
}

// ---------------- misc kernels ----------------
__global__ void k_zero(int sel, int n) {
    int i = blockIdx.x * blockDim.x + threadIdx.x;
    if (sel == 0) { if (i < n) g_agg1[i] = 0.f; }
    else if (sel == 1) { if (i < n) g_agg2[i] = 0.f; }
    else {
        if (i < GG * HH) { g_gsum[i] = 0.f; g_gsq[i] = 0.f; }
        if (i < GG) g_gcnt[i] = 0.f;
    }
}

template <int F, int WP>
__global__ void k_w12pack(const float* __restrict__ W1, const float* __restrict__ W2,
                          uint2* __restrict__ out) {
    int n = blockIdx.x;
    int kp = threadIdx.x;
    if (kp >= WP) return;
    int k0 = 2 * kp, k1 = 2 * kp + 1;
    float a0 = 0.f, a1 = 0.f;
    for (int m = 0; m < 64; m++) {
        float w2 = W2[m * 128 + n];
        if (k0 < F) a0 += W1[k0 * 64 + m] * w2;
        if (k1 < F) a1 += W1[k1 * 64 + m] * w2;
    }
    out[n * WP + kp] = splitbf2p(make_float2(a0, a1));
}

// pack 13 [128,128] node weight matrices, n-major kpairs, width 68
__global__ void k_wpackAll(const float* p0, const float* p1, const float* p2,
                           const float* p3, const float* p4, const float* p5,
                           const float* p6, const float* p7, const float* p8,
                           const float* p9, const float* p10, const float* p11,
                           const float* p12) {
    const float* srcs[13] = {p0, p1, p2, p3, p4, p5, p6, p7, p8, p9, p10, p11, p12};
    const float* W = srcs[blockIdx.x];
    uint2* dst = g_wpk + blockIdx.x * (128 * 68);
    int n = threadIdx.x;
    for (int kp = 0; kp < 64; kp++) {
        float w0 = W[(2 * kp) * 128 + n];
        float w1 = W[(2 * kp + 1) * 128 + n];
        dst[n * 68 + kp] = splitbf2p(make_float2(w0, w1));
    }
}

// ---------------- node GEMM (512 thr, m128) — used only for xh ----------------
template <bool DUAL, bool SW, bool RES>
__global__ __launch_bounds__(512, 1) void k_gemmT(
    const float* __restrict__ A, const float* __restrict__ Wa,
    const float* __restrict__ B, const float* __restrict__ Wb,
    const float* __restrict__ bias, const float* __restrict__ R,
    float* __restrict__ out, int n) {
    constexpr int WW = 68;
    extern __shared__ uint2 shu[];
    uint2* Ws  = shu;
    uint2* As2 = shu + 128 * WW;
    int tid = threadIdx.x, w = tid >> 5, lane = tid & 31, g = lane >> 2, t = lane & 3;
    int wg = w >> 2, wn = w & 3;
    int r0 = blockIdx.x * 128;

    float acc[2][4][4];
    #pragma unroll
    for (int mf = 0; mf < 2; mf++)
        #pragma unroll
        for (int nf = 0; nf < 4; nf++)
            #pragma unroll
            for (int i = 0; i < 4; i++) acc[mf][nf][i] = 0.f;

    const int NPASS = DUAL ? 2 : 1;
    for (int p = 0; p < NPASS; p++) {
        const float* Ain = p ? B : A;
        const float* Win = p ? Wb : Wa;
        __syncthreads();
        for (int i = tid; i < 128 * 64; i += 512) {
            int nn = i & 127, kp = i >> 7;
            float w0 = Win[(2 * kp) * 128 + nn];
            float w1 = Win[(2 * kp + 1) * 128 + nn];
            Ws[nn * WW + kp] = splitbf2p(make_float2(w0, w1));
        }
        for (int i = tid; i < 128 * 64; i += 512) {
            int r = i >> 6, kp = i & 63;
            int row = r0 + r;
            float2 v = (row < n) ? *(const float2*)(Ain + (size_t)row * 128 + 2 * kp)
                                 : make_float2(0.f, 0.f);
            As2[r * WW + kp] = splitbf2p(v);
        }
        __syncthreads();
        #pragma unroll
        for (int ks = 0; ks < 8; ks++) {
            int kp0 = ks * 8;
            uint32_t bh[4][2], bl[4][2];
            #pragma unroll
            for (int nf = 0; nf < 4; nf++) {
                int nn = wn * 32 + nf * 8 + g;
                uint2 b0 = Ws[nn * WW + kp0 + t];
                uint2 b1 = Ws[nn * WW + kp0 + t + 4];
                bh[nf][0] = b0.x; bl[nf][0] = b0.y;
                bh[nf][1] = b1.x; bl[nf][1] = b1.y;
            }
            #pragma unroll
            for (int mf = 0; mf < 2; mf++) {
                int r = wg * 32 + mf * 16 + g;
                uint2 a0 = As2[r * WW + kp0 + t];
                uint2 a1 = As2[(r + 8) * WW + kp0 + t];
                uint2 a2 = As2[r * WW + kp0 + t + 4];
                uint2 a3 = As2[(r + 8) * WW + kp0 + t + 4];
                #pragma unroll
                for (int nf = 0; nf < 4; nf++)
                    mma3(acc[mf][nf], a0, a1, a2, a3,
                         bh[nf][0], bh[nf][1], bl[nf][0], bl[nf][1]);
            }
        }
    }
    float2 bb[4];
    #pragma unroll
    for (int nf = 0; nf < 4; nf++) bb[nf] = *(const float2*)&bias[wn * 32 + nf * 8 + 2 * t];
    #pragma unroll
    for (int mf = 0; mf < 2; mf++) {
        #pragma unroll
        for (int half = 0; half < 2; half++) {
            int row = r0 + wg * 32 + mf * 16 + g + 8 * half;
            if (row < n) {
                #pragma unroll
                for (int nf = 0; nf < 4; nf++) {
                    int col = wn * 32 + nf * 8 + 2 * t;
                    float vx = acc[mf][nf][2 * half + 0] + bb[nf].x;
                    float vy = acc[mf][nf][2 * half + 1] + bb[nf].y;
                    if (SW) { vx = vx / (1.f + expf(-vx)); vy = vy / (1.f + expf(-vy)); }
                    if (RES) {
                        float2 rv = *(const float2*)&R[(size_t)row * 128 + col];
                        vx += rv.x; vy += rv.y;
                    }
                    *(float2*)&out[(size_t)row * 128 + col] = make_float2(vx, vy);
                }
            }
        }
    }
}

// ---------------- node GEMM: 256 thr, m64 tile, B-frags from L1 (packed) ----------------
template <bool DUAL, bool SW, bool RES>
__global__ __launch_bounds__(256, 3) void k_gemm2(
    const float* __restrict__ A, const uint2* __restrict__ Wa,
    const float* __restrict__ B, const uint2* __restrict__ Wb,
    const float* __restrict__ bias, const float* __restrict__ R,
    float* __restrict__ out, int n) {
    constexpr int WW = 68;
    extern __shared__ uint2 shu[];
    uint2* As2 = shu;   // [64][68]
    int tid = threadIdx.x, w = tid >> 5, lane = tid & 31, g = lane >> 2, t = lane & 3;
    int wg = w >> 2, wn = w & 3;
    int r0 = blockIdx.x * 64;

    float acc[2][4][4];
    #pragma unroll
    for (int mf = 0; mf < 2; mf++)
        #pragma unroll
        for (int nf = 0; nf < 4; nf++)
            #pragma unroll
            for (int i = 0; i < 4; i++) acc[mf][nf][i] = 0.f;

    const int NPASS = DUAL ? 2 : 1;
    for (int p = 0; p < NPASS; p++) {
        const float* Ain = p ? B : A;
        const uint2* Wp = p ? Wb : Wa;
        __syncthreads();
        for (int i = tid; i < 64 * 64; i += 256) {
            int r = i >> 6, kp = i & 63;
            int row = r0 + r;
            float2 v = (row < n) ? *(const float2*)(Ain + (size_t)row * 128 + 2 * kp)
                                 : make_float2(0.f, 0.f);
            As2[r * WW + kp] = splitbf2p(v);
        }
        __syncthreads();
        #pragma unroll
        for (int ks = 0; ks < 8; ks++) {
            int kp0 = ks * 8;
            uint32_t bh[4][2], bl[4][2];
            #pragma unroll
            for (int nf = 0; nf < 4; nf++) {
                int nn = wn * 32 + nf * 8 + g;
                uint2 b0 = __ldg(&Wp[nn * WW + kp0 + t]);
                uint2 b1 = __ldg(&Wp[nn * WW + kp0 + t + 4]);
                bh[nf][0] = b0.x; bl[nf][0] = b0.y;
                bh[nf][1] = b1.x; bl[nf][1] = b1.y;
            }
            #pragma unroll
            for (int mf = 0; mf < 2; mf++) {
                int r = wg * 32 + mf * 16 + g;
                uint2 a0 = As2[r * WW + kp0 + t];
                uint2 a1 = As2[(r + 8) * WW + kp0 + t];
                uint2 a2 = As2[r * WW + kp0 + t + 4];
                uint2 a3 = As2[(r + 8) * WW + kp0 + t + 4];
                #pragma unroll
                for (int nf = 0; nf < 4; nf++)
                    mma3(acc[mf][nf], a0, a1, a2, a3,
                         bh[nf][0], bh[nf][1], bl[nf][0], bl[nf][1]);
            }
        }
    }
    float2 bb[4];
    #pragma unroll
    for (int nf = 0; nf < 4; nf++) bb[nf] = *(const float2*)&bias[wn * 32 + nf * 8 + 2 * t];
    #pragma unroll
    for (int mf = 0; mf < 2; mf++) {
        #pragma unroll
        for (int half = 0; half < 2; half++) {
            int row = r0 + wg * 32 + mf * 16 + g + 8 * half;
            if (row < n) {
                #pragma unroll
                for (int nf = 0; nf < 4; nf++) {
                    int col = wn * 32 + nf * 8 + 2 * t;
                    float vx = acc[mf][nf][2 * half + 0] + bb[nf].x;
                    float vy = acc[mf][nf][2 * half + 1] + bb[nf].y;
                    if (SW) { vx = vx / (1.f + expf(-vx)); vy = vy / (1.f + expf(-vy)); }
                    if (RES) {
                        float2 rv = *(const float2*)&R[(size_t)row * 128 + col];
                        vx += rv.x; vy += rv.y;
                    }
                    *(float2*)&out[(size_t)row * 128 + col] = make_float2(vx, vy);
                }
            }
        }
    }
}

// ---------------- pipelined edge GEMM (F=147): 256 thr, m64xn32 per warp ----------------
__global__ __launch_bounds__(256, 1) void k_edgeP(
    const float* __restrict__ feat, const uint2* __restrict__ wpk,
    const int* __restrict__ ei, const float* __restrict__ xh,
    float* __restrict__ agg, int E) {
    constexpr int WP = 84;   // B kpair width
    constexpr int AW = 12;   // A chunk buf width (8 kpairs + 4 pad)
    extern __shared__ uint2 shu[];
    uint2* Bs  = shu;                        // [128][84]
    uint2* Ab0 = shu + 128 * WP;             // [128][12]
    uint2* Ab1 = Ab0 + 128 * AW;             // [128][12]
    float* fs  = (float*)(Ab1 + 128 * AW);   // [64][132]
    int* srcs = (int*)(fs + 64 * 132);
    int* dsts = srcs + 128;

    int tid = threadIdx.x, w = tid >> 5, lane = tid & 31, g = lane >> 2, t = lane & 3;
    int wg = w >> 2, wn = w & 3;   // wg 0..1 (m64), wn 0..3 (n32)
    int lr = tid >> 1, t2 = tid & 1;  // staging: 2 threads/row, 8 floats each

    for (int i = tid; i < 128 * WP; i += 256) Bs[i] = wpk[i];

    int ntiles = (E + 127) >> 7;

    float lf[8];
    // prologue: stage chunk0 of first tile
    if ((int)blockIdx.x < ntiles) {
        int ed = blockIdx.x * 128 + lr;
        const float* fr = feat + (size_t)ed * 147 + 8 * t2;
        #pragma unroll
        for (int j = 0; j < 8; j++) lf[j] = (ed < E) ? fr[j] : 0.f;
        uint2 u0 = splitbf2p(make_float2(lf[0], lf[1]));
        uint2 u1 = splitbf2p(make_float2(lf[2], lf[3]));
        uint2 u2 = splitbf2p(make_float2(lf[4], lf[5]));
        uint2 u3 = splitbf2p(make_float2(lf[6], lf[7]));
        *(uint4*)&Ab0[lr * AW + 4 * t2]     = make_uint4(u0.x, u0.y, u1.x, u1.y);
        *(uint4*)&Ab0[lr * AW + 4 * t2 + 2] = make_uint4(u2.x, u2.y, u3.x, u3.y);
    }
    __syncthreads();

    for (int tile = blockIdx.x; tile < ntiles; tile += gridDim.x) {
        float acc[4][4][4];
        #pragma unroll
        for (int mf = 0; mf < 4; mf++)
            #pragma unroll
            for (int nf = 0; nf < 4; nf++)
                #pragma unroll
                for (int i = 0; i < 4; i++) acc[mf][nf][i] = 0.f;

        if (tid < 128) {
            int ed = tile * 128 + tid;
            srcs[tid] = (ed < E) ? ei[ed] : 0;
            dsts[tid] = (ed < E) ? ei[(size_t)E + ed] : 0;
        }

        for (int c = 0; c < 10; c++) {
            uint2* cur = (c & 1) ? Ab1 : Ab0;
            uint2* nxt = (c & 1) ? Ab0 : Ab1;
            int nt = tile, nc = c + 1;
            if (nc == 10) { nt = tile + gridDim.x; nc = 0; }
            bool dl = (nt < ntiles);
            if (dl) {
                int ed = nt * 128 + lr;
                int kb = 16 * nc + 8 * t2;
                const float* fr = feat + (size_t)ed * 147 + kb;
                #pragma unroll
                for (int j = 0; j < 8; j++)
                    lf[j] = (ed < E && (kb + j) < 147) ? fr[j] : 0.f;
            }
            // mma on current chunk
            {
                int kbp = 8 * c;
                uint32_t bh[4][2], bl[4][2];
                #pragma unroll
                for (int nf = 0; nf < 4; nf++) {
                    int nn = wn * 32 + nf * 8 + g;
                    uint2 b0 = Bs[nn * WP + kbp + t];
                    uint2 b1 = Bs[nn * WP + kbp + t + 4];
                    bh[nf][0] = b0.x; bl[nf][0] = b0.y;
                    bh[nf][1] = b1.x; bl[nf][1] = b1.y;
                }
                #pragma unroll
                for (int mf = 0; mf < 4; mf++) {
                    int rr = wg * 64 + mf * 16 + g;
                    uint2 a0 = cur[rr * AW + t];
                    uint2 a1 = cur[(rr + 8) * AW + t];
                    uint2 a2 = cur[rr * AW + t + 4];
                    uint2 a3 = cur[(rr + 8) * AW + t + 4];
                    #pragma unroll
                    for (int nf = 0; nf < 4; nf++)
                        mma3(acc[mf][nf], a0, a1, a2, a3,
                             bh[nf][0], bh[nf][1], bl[nf][0], bl[nf][1]);
                }
            }
            if (dl) {
                uint2 u0 = splitbf2p(make_float2(lf[0], lf[1]));
                uint2 u1 = splitbf2p(make_float2(lf[2], lf[3]));
                uint2 u2 = splitbf2p(make_float2(lf[4], lf[5]));
                uint2 u3 = splitbf2p(make_float2(lf[6], lf[7]));
                *(uint4*)&nxt[lr * AW + 4 * t2]     = make_uint4(u0.x, u0.y, u1.x, u1.y);
                *(uint4*)&nxt[lr * AW + 4 * t2 + 2] = make_uint4(u2.x, u2.y, u3.x, u3.y);
            }
            __syncthreads();
        }
        // epilogue: two 64-row halves via fs
        #pragma unroll
        for (int h = 0; h < 2; h++) {
            __syncthreads();
            if (wg == h) {
                #pragma unroll
                for (int mf = 0; mf < 4; mf++) {
                    int rb = mf * 16 + g;
                    #pragma unroll
                    for (int nf = 0; nf < 4; nf++) {
                        int col = wn * 32 + nf * 8 + 2 * t;
                        *(float2*)&fs[rb * 132 + col] =
                            make_float2(acc[mf][nf][0], acc[mf][nf][1]);
                        *(float2*)&fs[(rb + 8) * 132 + col] =
                            make_float2(acc[mf][nf][2], acc[mf][nf][3]);
                    }
                }
            }
            __syncthreads();
            int rl = tid >> 2, q = tid & 3;
            int ed = tile * 128 + h * 64 + rl;
            if (ed < E) {
                int s = srcs[h * 64 + rl], d = dsts[h * 64 + rl];
                const float4* xr = (const float4*)(xh + (size_t)s * 128);
                float4* ar = (float4*)(agg + (size_t)d * 128);
                #pragma unroll
                for (int i = 0; i < 8; i++) {
                    int c4 = q + 4 * i;
                    float4 f = *(float4*)&fs[rl * 132 + 4 * c4];
                    float4 xv = xr[c4];
                    atomicAdd(ar + c4,
                              make_float4(f.x * xv.x, f.y * xv.y, f.z * xv.z, f.w * xv.w));
                }
            }
        }
        __syncthreads();
    }
}

// ---------------- edge GEMM (F=21), single-chunk ----------------
__global__ __launch_bounds__(512, 1) void k_edgeS(
    const float* __restrict__ feat, const uint2* __restrict__ wpk,
    const int* __restrict__ ei, const float* __restrict__ xh,
    float* __restrict__ agg, int E) {
    constexpr int F = 21;
    constexpr int WP = 20;
    extern __shared__ uint2 shu[];
    uint2* Bs  = shu;
    uint2* As2 = shu + 128 * WP;
    float* fs = (float*)(As2 + 128 * WP);
    int* srcs = (int*)(fs + 64 * 132);
    int* dsts = srcs + 128;

    int tid = threadIdx.x, w = tid >> 5, lane = tid & 31, g = lane >> 2, t = lane & 3;
    int wg = w >> 2, wn = w & 3;

    for (int i = tid; i < 128 * WP; i += 512) Bs[i] = wpk[i];

    int ntiles = (E + 127) >> 7;
    for (int tile = blockIdx.x; tile < ntiles; tile += gridDim.x) {
        float acc[2][4][4];
        #pragma unroll
        for (int mf = 0; mf < 2; mf++)
            #pragma unroll
            for (int nf = 0; nf < 4; nf++)
                #pragma unroll
                for (int i = 0; i < 4; i++) acc[mf][nf][i] = 0.f;

        __syncthreads();
        if (tid < 128) {
            int ed = tile * 128 + tid;
            srcs[tid] = (ed < E) ? ei[ed] : 0;
            dsts[tid] = (ed < E) ? ei[(size_t)E + ed] : 0;
        }
        for (int i = tid; i < 128 * WP; i += 512) {
            int r = i / WP, kp = i - r * WP;
            int ed = tile * 128 + r;
            int k0 = 2 * kp;
            float v0 = 0.f, v1 = 0.f;
            if (ed < E && k0 < F) {
                const float* fr = feat + (size_t)ed * F;
                v0 = fr[k0];
                if (k0 + 1 < F) v1 = fr[k0 + 1];
            }
            As2[r * WP + kp] = splitbf2p(make_float2(v0, v1));
        }
        __syncthreads();
        #pragma unroll
        for (int ks = 0; ks < 2; ks++) {
            int kp0 = ks * 8;
            uint32_t bh[4][2], bl[4][2];
            #pragma unroll
            for (int nf = 0; nf < 4; nf++) {
                int nn = wn * 32 + nf * 8 + g;
                uint2 b0 = Bs[nn * WP + kp0 + t];
                uint2 b1 = Bs[nn * WP + kp0 + t + 4];
                bh[nf][0] = b0.x; bl[nf][0] = b0.y;
                bh[nf][1] = b1.x; bl[nf][1] = b1.y;
            }
            #pragma unroll
            for (int mf = 0; mf < 2; mf++) {
                int r = wg * 32 + mf * 16 + g;
                uint2 a0 = As2[r * WP + kp0 + t];
                uint2 a1 = As2[(r + 8) * WP + kp0 + t];
                uint2 a2 = As2[r * WP + kp0 + t + 4];
                uint2 a3 = As2[(r + 8) * WP + kp0 + t + 4];
                #pragma unroll
                for (int nf = 0; nf < 4; nf++)
                    mma3(acc[mf][nf], a0, a1, a2, a3,
                         bh[nf][0], bh[nf][1], bl[nf][0], bl[nf][1]);
            }
        }
        #pragma unroll
        for (int h = 0; h < 2; h++) {
            __syncthreads();
            if ((wg >> 1) == h) {
                int rbase = (wg & 1) * 32;
                #pragma unroll
                for (int mf = 0; mf < 2; mf++) {
                    int rb = rbase + mf * 16 + g;
                    #pragma unroll
                    for (int nf = 0; nf < 4; nf++) {
                        int col = wn * 32 + nf * 8 + 2 * t;
                        *(float2*)&fs[rb * 132 + col] =
                            make_float2(acc[mf][nf][0], acc[mf][nf][1]);
                        *(float2*)&fs[(rb + 8) * 132 + col] =
                            make_float2(acc[mf][nf][2], acc[mf][nf][3]);
                    }
                }
            }
            __syncthreads();
            int rl = tid >> 3, q = tid & 7;
            int ed = tile * 128 + h * 64 + rl;
            if (ed < E) {
                int s = srcs[h * 64 + rl], d = dsts[h * 64 + rl];
                const float4* xr = (const float4*)(xh + (size_t)s * 128);
                float4* ar = (float4*)(agg + (size_t)d * 128);
                #pragma unroll
                for (int i = 0; i < 4; i++) {
                    int c4 = q + 8 * i;
                    float4 f = *(float4*)&fs[rl * 132 + 4 * c4];
                    float4 xv = xr[c4];
                    atomicAdd(ar + c4,
                              make_float4(f.x * xv.x, f.y * xv.y, f.z * xv.z, f.w * xv.w));
                }
            }
        }
    }
}

// ---------------- GraphNorm pieces ----------------
__global__ void k_gsum(const float* __restrict__ h, const int* __restrict__ batch, int n) {
    int idx = blockIdx.x * blockDim.x + threadIdx.x;
    if (idx >= n * HH) return;
    int i = idx >> 7, c = idx & 127;
    int g = batch[i];
    if (c == 0) atomicAdd(&g_gcnt[g], 1.f);
    atomicAdd(&g_gsum[g * HH + c], h[idx]);
}

__global__ void k_center(const float* __restrict__ h, const int* __restrict__ batch,
                         const float* __restrict__ ms, int n) {
    int idx = blockIdx.x * blockDim.x + threadIdx.x;
    if (idx >= n * HH) return;
    int i = idx >> 7, c = idx & 127;
    int g = batch[i];
    float cnt = g_gcnt[g]; if (cnt < 1.f) cnt = 1.f;
    float mean = g_gsum[g * HH + c] / cnt;
    float o = h[idx] - mean * ms[c];
    g_on[idx] = o;
    atomicAdd(&g_gsq[g * HH + c], o * o);
}

__global__ void k_norm(const int* __restrict__ batch,
                       const float* __restrict__ w, const float* __restrict__ b, int n) {
    int idx = blockIdx.x * blockDim.x + threadIdx.x;
    if (idx >= n * HH) return;
    int i = idx >> 7, c = idx & 127;
    int g = batch[i];
    float cnt = g_gcnt[g]; if (cnt < 1.f) cnt = 1.f;
    float var = g_gsq[g * HH + c] / cnt;
    g_on[idx] = w[c] * g_on[idx] * rsqrtf(var + 1e-5f) + b[c];
}

// ---------------- launch ----------------
extern "C" void kernel_launch(void* const* d_in, const int* in_sizes, int n_in,
                              void* d_out, int out_size) {
    const float* x          = (const float*)d_in[0];
    const float* feature1   = (const float*)d_in[1];
    const float* feature2   = (const float*)d_in[2];
    const int*   edge_index = (const int*)d_in[3];
    const int*   batch      = (const int*)d_in[4];
    const float* lin_w        = (const float*)d_in[5];
    const float* lin_b        = (const float*)d_in[6];
    const float* f1_w1        = (const float*)d_in[7];
    const float* f1_w2        = (const float*)d_in[8];
    const float* f2_w1        = (const float*)d_in[9];
    const float* f2_w2        = (const float*)d_in[10];
    const float* conv1_rel_w  = (const float*)d_in[11];
    const float* conv1_rel_b  = (const float*)d_in[12];
    const float* conv1_root_w = (const float*)d_in[13];
    const float* conv2_rel_w  = (const float*)d_in[14];
    const float* conv2_rel_b  = (const float*)d_in[15];
    const float* conv2_root_w = (const float*)d_in[16];
    const float* lin1_w       = (const float*)d_in[17];
    const float* lin1_b       = (const float*)d_in[18];
    const float* lin2_w       = (const float*)d_in[19];
    const float* lin2_b       = (const float*)d_in[20];
    const float* lincat_w     = (const float*)d_in[21];
    const float* lincat_b     = (const float*)d_in[22];
    const float* norm_w       = (const float*)d_in[23];
    const float* norm_b       = (const float*)d_in[24];
    const float* norm_ms      = (const float*)d_in[25];
    const float* lins_w       = (const float*)d_in[26];
    const float* lins_b       = (const float*)d_in[27];
    const float* final_w      = (const float*)d_in[28];
    const float* final_b      = (const float*)d_in[29];

    int N_ = in_sizes[0] / HH;
    int E_ = in_sizes[3] / 2;

    static float *p_xh = nullptr, *p_agg1, *p_agg2, *p_c, *p_ha, *p_hb, *p_on;
    static uint2 *p_wa, *p_wb, *p_wpk;
    if (!p_xh) {
        cudaGetSymbolAddress((void**)&p_xh,   g_xh);
        cudaGetSymbolAddress((void**)&p_agg1, g_agg1);
        cudaGetSymbolAddress((void**)&p_agg2, g_agg2);
        cudaGetSymbolAddress((void**)&p_c,    g_c);
        cudaGetSymbolAddress((void**)&p_ha,   g_ha);
        cudaGetSymbolAddress((void**)&p_hb,   g_hb);
        cudaGetSymbolAddress((void**)&p_on,   g_on);
        cudaGetSymbolAddress((void**)&p_wa,   g_w12a);
        cudaGetSymbolAddress((void**)&p_wb,   g_w12b);
        cudaGetSymbolAddress((void**)&p_wpk,  g_wpk);
    }

    const int sme1 = 128 * 84 * 8 + 2 * 128 * 12 * 8 + 64 * 132 * 4 + 1024;  // 145,408
    const int sme2 = 2 * 128 * 20 * 8 + 64 * 132 * 4 + 1024;                 // 75,776
    const int smg  = 2 * 128 * 68 * 8 + 256;                                 // 139,520
    const int smg2 = 64 * 68 * 8 + 128;                                      // 34,944
    static bool attr_done = false;
    if (!attr_done) {
        cudaFuncSetAttribute(k_edgeP, cudaFuncAttributeMaxDynamicSharedMemorySize, sme1);
        cudaFuncSetAttribute(k_edgeS, cudaFuncAttributeMaxDynamicSharedMemorySize, sme2);
        cudaFuncSetAttribute(k_gemmT<false, true, false>, cudaFuncAttributeMaxDynamicSharedMemorySize, smg);
        cudaFuncSetAttribute(k_gemm2<true, false, false>,  cudaFuncAttributeMaxDynamicSharedMemorySize, smg2);
        cudaFuncSetAttribute(k_gemm2<false, true, false>,  cudaFuncAttributeMaxDynamicSharedMemorySize, smg2);
        cudaFuncSetAttribute(k_gemm2<true, false, true>,   cudaFuncAttributeMaxDynamicSharedMemorySize, smg2);
        cudaFuncSetAttribute(k_gemm2<false, true, true>,   cudaFuncAttributeMaxDynamicSharedMemorySize, smg2);
        cudaFuncSetAttribute(k_gemm2<false, false, false>, cudaFuncAttributeMaxDynamicSharedMemorySize, smg2);
        attr_done = true;
    }

    int NH_ = N_ * HH;
    int gZ = (NH_ + 255) / 256;
    int gB128 = (N_ + 127) / 128;
    int gB64 = (N_ + 63) / 64;
    const int WMAT = 128 * 68;

    // launch order: index 3 = k_edgeP (profiling target)
    k_w12pack<147, 84><<<128, 84>>>(f1_w1, f1_w2, p_wa);                                  // 0
    k_zero<<<gZ, 256>>>(0, NH_);                                                          // 1
    k_gemmT<false, true, false><<<gB128, 512, smg>>>(x, lin_w, nullptr, nullptr, lin_b, nullptr, p_xh, N_);  // 2
    k_edgeP<<<148, 256, sme1>>>(feature1, p_wa, edge_index, p_xh, p_agg1, E_);            // 3
    k_wpackAll<<<13, 128>>>(lin_w, conv1_rel_w, conv1_root_w, conv2_rel_w, conv2_root_w,
                            lin1_w, lin2_w, lincat_w, lincat_w + HH * HH,
                            lins_w, lins_w + HH * HH, lins_w + 2 * HH * HH, final_w);     // 4
    k_w12pack<21, 20><<<128, 20>>>(f2_w1, f2_w2, p_wb);                                   // 5
    k_zero<<<gZ, 256>>>(1, NH_);                                                          // 6
    k_edgeS<<<296, 512, sme2>>>(feature2, p_wb, edge_index, p_xh, p_agg2, E_);            // 7

    // conv1 / lin1
    k_gemm2<true, false, false><<<gB64, 256, smg2>>>(p_agg1, p_wpk + 1 * WMAT, p_xh, p_wpk + 2 * WMAT, conv1_rel_b, nullptr, p_c, N_);
    k_gemm2<false, true, false><<<gB64, 256, smg2>>>(p_c, p_wpk + 5 * WMAT, nullptr, nullptr, lin1_b, nullptr, p_agg1, N_);
    // conv2 / lin2
    k_gemm2<true, false, false><<<gB64, 256, smg2>>>(p_agg2, p_wpk + 3 * WMAT, p_xh, p_wpk + 4 * WMAT, conv2_rel_b, nullptr, p_c, N_);
    k_gemm2<false, true, false><<<gB64, 256, smg2>>>(p_c, p_wpk + 6 * WMAT, nullptr, nullptr, lin2_b, nullptr, p_agg2, N_);

    // h = cat(h1,h2) @ lincat + b + xh
    k_gemm2<true, false, true><<<gB64, 256, smg2>>>(p_agg1, p_wpk + 7 * WMAT, p_agg2, p_wpk + 8 * WMAT, lincat_b, p_xh, p_ha, N_);

    // residual lins
    k_gemm2<false, true, true><<<gB64, 256, smg2>>>(p_ha, p_wpk + 9 * WMAT,  nullptr, nullptr, lins_b,          p_ha, p_hb, N_);
    k_gemm2<false, true, true><<<gB64, 256, smg2>>>(p_hb, p_wpk + 10 * WMAT, nullptr, nullptr, lins_b + HH,     p_hb, p_ha, N_);
    k_gemm2<false, true, true><<<gB64, 256, smg2>>>(p_ha, p_wpk + 11 * WMAT, nullptr, nullptr, lins_b + 2 * HH, p_ha, p_hb, N_);

    // GraphNorm
    k_zero<<<(GG * HH + 255) / 256, 256>>>(2, NH_);
    k_gsum<<<gZ, 256>>>(p_hb, batch, N_);
    k_center<<<gZ, 256>>>(p_hb, batch, norm_ms, N_);
    k_norm<<<gZ, 256>>>(batch, norm_w, norm_b, N_);

    // final projection
    k_gemm2<false, false, false><<<gB64, 256, smg2>>>(p_on, p_wpk + 12 * WMAT, nullptr, nullptr, final_b, nullptr, (float*)d_out, N_);
}

// round 11
// speedup vs baseline: 1.1359x; 1.1359x over previous
#include <cuda_runtime.h>
#include <cuda_bf16.h>
#include <cstdint>
#include <math.h>

#define HH 128
#define GG 512
#define MAXN 50000
#define NHH (MAXN * HH)

// ---------------- device scratch ----------------
__device__ float g_xh[NHH];
__device__ float g_agg1[NHH];
__device__ float g_agg2[NHH];
__device__ float g_c[NHH];
__device__ float g_ha[NHH];
__device__ float g_hb[NHH];
__device__ float g_on[NHH];
__device__ uint2 g_w12a[128 * 84];       // packed split-bf16 W12 (feature1)
__device__ uint2 g_w12b[128 * 20];       // (feature2)
__device__ uint2 g_wpk[13 * 128 * 68];   // packed node weights

// ---------------- bf16 split helpers ----------------
__device__ __forceinline__ uint2 splitbf2p(float2 v) {
    __nv_bfloat162 h = __float22bfloat162_rn(v);
    float2 hv = __bfloat1622float2(h);
    __nv_bfloat162 l = __float22bfloat162_rn(make_float2(v.x - hv.x, v.y - hv.y));
    uint2 r;
    r.x = *reinterpret_cast<uint32_t*>(&h);
    r.y = *reinterpret_cast<uint32_t*>(&l);
    return r;
}

__device__ __forceinline__ void mma16(float* d, uint32_t a0, uint32_t a1, uint32_t a2,
                                      uint32_t a3, uint32_t b0, uint32_t b1) {
    asm volatile(
        "mma.sync.aligned.m16n8k16.row.col.f32.bf16.bf16.f32 "
        "{%0,%1,%2,%3}, {%4,%5,%6,%7}, {%8,%9}, {%0,%1,%2,%3};\n"
        : "+f"(d[0]), "+f"(d[1]), "+f"(d[2]), "+f"(d[3])
        : "r"(a0), "r"(a1), "r"(a2), "r"(a3), "r"(b0), "r"(b1));
}

__device__ __forceinline__ void mma3(float* d, const uint2& a0, const uint2& a1,
                                     const uint2& a2, const uint2& a3,
                                     uint32_t bh0, uint32_t bh1, uint32_t bl0, uint32_t bl1) {
    mma16(d, a0.x, a1.x, a2.x, a3.x, bh0, bh1);
    mma16(d, a0.x, a1.x, a2.x, a3.x, bl0, bl1);
    mma16(d, a0.y, a1.y, a2.y, a3.y, bh0, bh1);
}

// ---------------- prep: all weight packing in one kernel ----------------
__global__ void k_prep_pack(const float* __restrict__ f1_w1, const float* __restrict__ f1_w2,
                            const float* __restrict__ f2_w1, const float* __restrict__ f2_w2,
                            const float* __restrict__ lin_w, const float* __restrict__ c1r,
                            const float* __restrict__ c1t, const float* __restrict__ c2r,
                            const float* __restrict__ c2t, const float* __restrict__ l1w,
                            const float* __restrict__ l2w, const float* __restrict__ lcw,
                            const float* __restrict__ lsw, const float* __restrict__ fw) {
    int b = blockIdx.x, tid = threadIdx.x;
    if (b < 128) {            // w12a: n = b, kp = tid
        if (tid < 84) {
            int k0 = 2 * tid, k1 = k0 + 1;
            float a0 = 0.f, a1 = 0.f;
            for (int m = 0; m < 64; m++) {
                float w2 = f1_w2[m * 128 + b];
                if (k0 < 147) a0 += f1_w1[k0 * 64 + m] * w2;
                if (k1 < 147) a1 += f1_w1[k1 * 64 + m] * w2;
            }
            g_w12a[b * 84 + tid] = splitbf2p(make_float2(a0, a1));
        }
    } else if (b < 256) {     // w12b: n = b-128
        int n = b - 128;
        if (tid < 20) {
            int k0 = 2 * tid, k1 = k0 + 1;
            float a0 = 0.f, a1 = 0.f;
            for (int m = 0; m < 64; m++) {
                float w2 = f2_w2[m * 128 + n];
                if (k0 < 21) a0 += f2_w1[k0 * 64 + m] * w2;
                if (k1 < 21) a1 += f2_w1[k1 * 64 + m] * w2;
            }
            g_w12b[n * 20 + tid] = splitbf2p(make_float2(a0, a1));
        }
    } else {                  // node weights: matrix m = b-256
        int m = b - 256;
        if (tid < 128 && m < 13) {
            const float* srcs[13] = {lin_w, c1r, c1t, c2r, c2t, l1w, l2w,
                                     lcw, lcw + HH * HH, lsw, lsw + HH * HH,
                                     lsw + 2 * HH * HH, fw};
            const float* W = srcs[m];
            uint2* dst = g_wpk + m * (128 * 68);
            for (int kp = 0; kp < 64; kp++) {
                float w0 = W[(2 * kp) * 128 + tid];
                float w1 = W[(2 * kp + 1) * 128 + tid];
                dst[tid * 68 + kp] = splitbf2p(make_float2(w0, w1));
            }
        }
    }
}

__global__ void k_zero2(int n) {
    int i = blockIdx.x * blockDim.x + threadIdx.x;
    if (i < n) { g_agg1[i] = 0.f; g_agg2[i] = 0.f; }
}

// ---------------- node GEMM: 256 thr, m64 tile, B-frags from L1 (packed) ----------------
template <bool DUAL, bool SW, bool RES>
__global__ __launch_bounds__(256, 3) void k_gemm2(
    const float* __restrict__ A, const uint2* __restrict__ Wa,
    const float* __restrict__ B, const uint2* __restrict__ Wb,
    const float* __restrict__ bias, const float* __restrict__ R,
    float* __restrict__ out, int n) {
    constexpr int WW = 68;
    extern __shared__ uint2 shu[];
    uint2* As2 = shu;   // [64][68]
    int tid = threadIdx.x, w = tid >> 5, lane = tid & 31, g = lane >> 2, t = lane & 3;
    int wg = w >> 2, wn = w & 3;
    int r0 = blockIdx.x * 64;

    float acc[2][4][4];
    #pragma unroll
    for (int mf = 0; mf < 2; mf++)
        #pragma unroll
        for (int nf = 0; nf < 4; nf++)
            #pragma unroll
            for (int i = 0; i < 4; i++) acc[mf][nf][i] = 0.f;

    const int NPASS = DUAL ? 2 : 1;
    for (int p = 0; p < NPASS; p++) {
        const float* Ain = p ? B : A;
        const uint2* Wp = p ? Wb : Wa;
        __syncthreads();
        for (int i = tid; i < 64 * 64; i += 256) {
            int r = i >> 6, kp = i & 63;
            int row = r0 + r;
            float2 v = (row < n) ? *(const float2*)(Ain + (size_t)row * 128 + 2 * kp)
                                 : make_float2(0.f, 0.f);
            As2[r * WW + kp] = splitbf2p(v);
        }
        __syncthreads();
        #pragma unroll
        for (int ks = 0; ks < 8; ks++) {
            int kp0 = ks * 8;
            uint32_t bh[4][2], bl[4][2];
            #pragma unroll
            for (int nf = 0; nf < 4; nf++) {
                int nn = wn * 32 + nf * 8 + g;
                uint2 b0 = __ldg(&Wp[nn * WW + kp0 + t]);
                uint2 b1 = __ldg(&Wp[nn * WW + kp0 + t + 4]);
                bh[nf][0] = b0.x; bl[nf][0] = b0.y;
                bh[nf][1] = b1.x; bl[nf][1] = b1.y;
            }
            #pragma unroll
            for (int mf = 0; mf < 2; mf++) {
                int r = wg * 32 + mf * 16 + g;
                uint2 a0 = As2[r * WW + kp0 + t];
                uint2 a1 = As2[(r + 8) * WW + kp0 + t];
                uint2 a2 = As2[r * WW + kp0 + t + 4];
                uint2 a3 = As2[(r + 8) * WW + kp0 + t + 4];
                #pragma unroll
                for (int nf = 0; nf < 4; nf++)
                    mma3(acc[mf][nf], a0, a1, a2, a3,
                         bh[nf][0], bh[nf][1], bl[nf][0], bl[nf][1]);
            }
        }
    }
    float2 bb[4];
    #pragma unroll
    for (int nf = 0; nf < 4; nf++) bb[nf] = *(const float2*)&bias[wn * 32 + nf * 8 + 2 * t];
    #pragma unroll
    for (int mf = 0; mf < 2; mf++) {
        #pragma unroll
        for (int half = 0; half < 2; half++) {
            int row = r0 + wg * 32 + mf * 16 + g + 8 * half;
            if (row < n) {
                #pragma unroll
                for (int nf = 0; nf < 4; nf++) {
                    int col = wn * 32 + nf * 8 + 2 * t;
                    float vx = acc[mf][nf][2 * half + 0] + bb[nf].x;
                    float vy = acc[mf][nf][2 * half + 1] + bb[nf].y;
                    if (SW) { vx = vx / (1.f + expf(-vx)); vy = vy / (1.f + expf(-vy)); }
                    if (RES) {
                        float2 rv = *(const float2*)&R[(size_t)row * 128 + col];
                        vx += rv.x; vy += rv.y;
                    }
                    *(float2*)&out[(size_t)row * 128 + col] = make_float2(vx, vy);
                }
            }
        }
    }
}

// ---------------- fused edge GEMM: f1 (pipelined, R9 core) + f2, one tile pass ----------------
__global__ __launch_bounds__(512, 1) void k_edgeF(
    const float* __restrict__ feat1, const float* __restrict__ feat2,
    const uint2* __restrict__ w12a, const uint2* __restrict__ w12b,
    const int* __restrict__ ei, const float* __restrict__ xh,
    float* __restrict__ agg1, float* __restrict__ agg2, int E) {
    constexpr int WP = 84;    // f1 B kpair width
    constexpr int AW = 12;    // f1 A chunk buf width
    constexpr int WP2 = 20;   // f2 widths
    extern __shared__ uint2 shu[];
    uint2* Bs1 = shu;                         // [128][84]
    uint2* Ab0 = Bs1 + 128 * WP;              // [128][12]
    uint2* Ab1 = Ab0 + 128 * AW;              // [128][12]
    uint2* Bs2 = Ab1 + 128 * AW;              // [128][20]
    uint2* As2 = Bs2 + 128 * WP2;             // [128][20]
    float* fs  = (float*)(As2 + 128 * WP2);   // [64][132]
    int* srcs = (int*)(fs + 64 * 132);
    int* dsts = srcs + 128;

    int tid = threadIdx.x, w = tid >> 5, lane = tid & 31, g = lane >> 2, t = lane & 3;
    int wg = w >> 2, wn = w & 3;
    int lr = tid >> 2, t4 = tid & 3;

    for (int i = tid; i < 128 * WP; i += 512) Bs1[i] = w12a[i];
    for (int i = tid; i < 128 * WP2; i += 512) Bs2[i] = w12b[i];

    int ntiles = (E + 127) >> 7;

    float acc[2][4][4];
    auto epilogue = [&](int tile, float* aggp) {
        #pragma unroll
        for (int h = 0; h < 2; h++) {
            __syncthreads();
            if ((wg >> 1) == h) {
                int rbase = (wg & 1) * 32;
                #pragma unroll
                for (int mf = 0; mf < 2; mf++) {
                    int rb = rbase + mf * 16 + g;
                    #pragma unroll
                    for (int nf = 0; nf < 4; nf++) {
                        int col = wn * 32 + nf * 8 + 2 * t;
                        *(float2*)&fs[rb * 132 + col] =
                            make_float2(acc[mf][nf][0], acc[mf][nf][1]);
                        *(float2*)&fs[(rb + 8) * 132 + col] =
                            make_float2(acc[mf][nf][2], acc[mf][nf][3]);
                    }
                }
            }
            __syncthreads();
            int rl = tid >> 3, q = tid & 7;
            int ed = tile * 128 + h * 64 + rl;
            if (ed < E) {
                int s = srcs[h * 64 + rl], d = dsts[h * 64 + rl];
                const float4* xr = (const float4*)(xh + (size_t)s * 128);
                float4* ar = (float4*)(aggp + (size_t)d * 128);
                #pragma unroll
                for (int i = 0; i < 4; i++) {
                    int c4 = q + 8 * i;
                    float4 f = *(float4*)&fs[rl * 132 + 4 * c4];
                    float4 xv = xr[c4];
                    atomicAdd(ar + c4,
                              make_float4(f.x * xv.x, f.y * xv.y, f.z * xv.z, f.w * xv.w));
                }
            }
        }
    };

    float lf[4];
    // prologue: stage f1 chunk0 of first tile
    if ((int)blockIdx.x < ntiles) {
        int ed = blockIdx.x * 128 + lr;
        const float* fr = feat1 + (size_t)ed * 147 + 4 * t4;
        #pragma unroll
        for (int j = 0; j < 4; j++) lf[j] = (ed < E) ? fr[j] : 0.f;
        uint2 u0 = splitbf2p(make_float2(lf[0], lf[1]));
        uint2 u1 = splitbf2p(make_float2(lf[2], lf[3]));
        *(uint4*)&Ab0[lr * AW + 2 * t4] = make_uint4(u0.x, u0.y, u1.x, u1.y);
    }
    __syncthreads();

    for (int tile = blockIdx.x; tile < ntiles; tile += gridDim.x) {
        #pragma unroll
        for (int mf = 0; mf < 2; mf++)
            #pragma unroll
            for (int nf = 0; nf < 4; nf++)
                #pragma unroll
                for (int i = 0; i < 4; i++) acc[mf][nf][i] = 0.f;

        if (tid < 128) {
            int ed = tile * 128 + tid;
            srcs[tid] = (ed < E) ? ei[ed] : 0;
            dsts[tid] = (ed < E) ? ei[(size_t)E + ed] : 0;
        }
        // stage f2 features early (LDG latency hides under f1 mma phase)
        for (int i = tid; i < 128 * WP2; i += 512) {
            int r = i / WP2, kp = i - r * WP2;
            int ed = tile * 128 + r;
            int k0 = 2 * kp;
            float v0 = 0.f, v1 = 0.f;
            if (ed < E && k0 < 21) {
                const float* fr = feat2 + (size_t)ed * 21;
                v0 = fr[k0];
                if (k0 + 1 < 21) v1 = fr[k0 + 1];
            }
            As2[r * WP2 + kp] = splitbf2p(make_float2(v0, v1));
        }

        // ---- f1: 10 pipelined chunks ----
        for (int c = 0; c < 10; c++) {
            uint2* cur = (c & 1) ? Ab1 : Ab0;
            uint2* nxt = (c & 1) ? Ab0 : Ab1;
            int nt = tile, nc = c + 1;
            if (nc == 10) { nt = tile + gridDim.x; nc = 0; }
            bool dl = (nt < ntiles);
            if (dl) {
                int ed = nt * 128 + lr;
                int kb = 16 * nc + 4 * t4;
                const float* fr = feat1 + (size_t)ed * 147 + kb;
                #pragma unroll
                for (int j = 0; j < 4; j++)
                    lf[j] = (ed < E && (kb + j) < 147) ? fr[j] : 0.f;
            }
            {
                int kbp = 8 * c;
                uint32_t bh[4][2], bl[4][2];
                #pragma unroll
                for (int nf = 0; nf < 4; nf++) {
                    int nn = wn * 32 + nf * 8 + g;
                    uint2 b0 = Bs1[nn * WP + kbp + t];
                    uint2 b1 = Bs1[nn * WP + kbp + t + 4];
                    bh[nf][0] = b0.x; bl[nf][0] = b0.y;
                    bh[nf][1] = b1.x; bl[nf][1] = b1.y;
                }
                #pragma unroll
                for (int mf = 0; mf < 2; mf++) {
                    int rr = wg * 32 + mf * 16 + g;
                    uint2 a0 = cur[rr * AW + t];
                    uint2 a1 = cur[(rr + 8) * AW + t];
                    uint2 a2 = cur[rr * AW + t + 4];
                    uint2 a3 = cur[(rr + 8) * AW + t + 4];
                    #pragma unroll
                    for (int nf = 0; nf < 4; nf++)
                        mma3(acc[mf][nf], a0, a1, a2, a3,
                             bh[nf][0], bh[nf][1], bl[nf][0], bl[nf][1]);
                }
            }
            if (dl) {
                uint2 u0 = splitbf2p(make_float2(lf[0], lf[1]));
                uint2 u1 = splitbf2p(make_float2(lf[2], lf[3]));
                *(uint4*)&nxt[lr * AW + 2 * t4] = make_uint4(u0.x, u0.y, u1.x, u1.y);
            }
            __syncthreads();
        }
        epilogue(tile, agg1);

        // ---- f2: 2 k-steps from As2/Bs2 ----
        #pragma unroll
        for (int mf = 0; mf < 2; mf++)
            #pragma unroll
            for (int nf = 0; nf < 4; nf++)
                #pragma unroll
                for (int i = 0; i < 4; i++) acc[mf][nf][i] = 0.f;
        #pragma unroll
        for (int ks = 0; ks < 2; ks++) {
            int kp0 = ks * 8;
            uint32_t bh[4][2], bl[4][2];
            #pragma unroll
            for (int nf = 0; nf < 4; nf++) {
                int nn = wn * 32 + nf * 8 + g;
                uint2 b0 = Bs2[nn * WP2 + kp0 + t];
                uint2 b1 = Bs2[nn * WP2 + kp0 + t + 4];
                bh[nf][0] = b0.x; bl[nf][0] = b0.y;
                bh[nf][1] = b1.x; bl[nf][1] = b1.y;
            }
            #pragma unroll
            for (int mf = 0; mf < 2; mf++) {
                int rr = wg * 32 + mf * 16 + g;
                uint2 a0 = As2[rr * WP2 + kp0 + t];
                uint2 a1 = As2[(rr + 8) * WP2 + kp0 + t];
                uint2 a2 = As2[rr * WP2 + kp0 + t + 4];
                uint2 a3 = As2[(rr + 8) * WP2 + kp0 + t + 4];
                #pragma unroll
                for (int nf = 0; nf < 4; nf++)
                    mma3(acc[mf][nf], a0, a1, a2, a3,
                         bh[nf][0], bh[nf][1], bl[nf][0], bl[nf][1]);
            }
        }
        epilogue(tile, agg2);
        __syncthreads();
    }
}

// ---------------- fused GraphNorm (batch is sorted: block per graph) ----------------
__global__ __launch_bounds__(128) void k_gnorm(
    const float* __restrict__ h, const int* __restrict__ batch,
    const float* __restrict__ ms, const float* __restrict__ w,
    const float* __restrict__ b, float* __restrict__ out, int n) {
    int g = blockIdx.x;
    int c = threadIdx.x;
    // lower_bound for g and g+1
    int lo = 0, hi = n;
    while (lo < hi) { int mid = (lo + hi) >> 1; if (batch[mid] < g) lo = mid + 1; else hi = mid; }
    int start = lo;
    hi = n;
    while (lo < hi) { int mid = (lo + hi) >> 1; if (batch[mid] < g + 1) lo = mid + 1; else hi = mid; }
    int end = lo;
    int cnt = end - start;
    if (cnt <= 0) return;
    float fc = (float)cnt;

    // pass 1: mean (4 accumulators for MLP)
    float s0 = 0.f, s1 = 0.f, s2 = 0.f, s3 = 0.f;
    int r = start;
    for (; r + 3 < end; r += 4) {
        s0 += h[(size_t)r * 128 + c];
        s1 += h[(size_t)(r + 1) * 128 + c];
        s2 += h[(size_t)(r + 2) * 128 + c];
        s3 += h[(size_t)(r + 3) * 128 + c];
    }
    for (; r < end; r++) s0 += h[(size_t)r * 128 + c];
    float mean = (s0 + s1 + s2 + s3) / fc;
    float sub = mean * ms[c];

    // pass 2: center, write o, accumulate var
    float v0 = 0.f, v1 = 0.f;
    for (r = start; r + 1 < end; r += 2) {
        float o0 = h[(size_t)r * 128 + c] - sub;
        float o1 = h[(size_t)(r + 1) * 128 + c] - sub;
        out[(size_t)r * 128 + c] = o0;
        out[(size_t)(r + 1) * 128 + c] = o1;
        v0 += o0 * o0; v1 += o1 * o1;
    }
    for (; r < end; r++) {
        float o = h[(size_t)r * 128 + c] - sub;
        out[(size_t)r * 128 + c] = o;
        v0 += o * o;
    }
    float inv = rsqrtf((v0 + v1) / fc + 1e-5f);
    float wc = w[c] * inv, bc = b[c];

    // pass 3: scale + shift (L2-hot)
    for (r = start; r < end; r++) {
        size_t idx = (size_t)r * 128 + c;
        out[idx] = wc * out[idx] + bc;
    }
}

// ---------------- launch ----------------
extern "C" void kernel_launch(void* const* d_in, const int* in_sizes, int n_in,
                              void* d_out, int out_size) {
    const float* x          = (const float*)d_in[0];
    const float* feature1   = (const float*)d_in[1];
    const float* feature2   = (const float*)d_in[2];
    const int*   edge_index = (const int*)d_in[3];
    const int*   batch      = (const int*)d_in[4];
    const float* lin_w        = (const float*)d_in[5];
    const float* lin_b        = (const float*)d_in[6];
    const float* f1_w1        = (const float*)d_in[7];
    const float* f1_w2        = (const float*)d_in[8];
    const float* f2_w1        = (const float*)d_in[9];
    const float* f2_w2        = (const float*)d_in[10];
    const float* conv1_rel_w  = (const float*)d_in[11];
    const float* conv1_rel_b  = (const float*)d_in[12];
    const float* conv1_root_w = (const float*)d_in[13];
    const float* conv2_rel_w  = (const float*)d_in[14];
    const float* conv2_rel_b  = (const float*)d_in[15];
    const float* conv2_root_w = (const float*)d_in[16];
    const float* lin1_w       = (const float*)d_in[17];
    const float* lin1_b       = (const float*)d_in[18];
    const float* lin2_w       = (const float*)d_in[19];
    const float* lin2_b       = (const float*)d_in[20];
    const float* lincat_w     = (const float*)d_in[21];
    const float* lincat_b     = (const float*)d_in[22];
    const float* norm_w       = (const float*)d_in[23];
    const float* norm_b       = (const float*)d_in[24];
    const float* norm_ms      = (const float*)d_in[25];
    const float* lins_w       = (const float*)d_in[26];
    const float* lins_b       = (const float*)d_in[27];
    const float* final_w      = (const float*)d_in[28];
    const float* final_b      = (const float*)d_in[29];

    int N_ = in_sizes[0] / HH;
    int E_ = in_sizes[3] / 2;

    static float *p_xh = nullptr, *p_agg1, *p_agg2, *p_c, *p_ha, *p_hb, *p_on;
    static uint2 *p_wa, *p_wb, *p_wpk;
    if (!p_xh) {
        cudaGetSymbolAddress((void**)&p_xh,   g_xh);
        cudaGetSymbolAddress((void**)&p_agg1, g_agg1);
        cudaGetSymbolAddress((void**)&p_agg2, g_agg2);
        cudaGetSymbolAddress((void**)&p_c,    g_c);
        cudaGetSymbolAddress((void**)&p_ha,   g_ha);
        cudaGetSymbolAddress((void**)&p_hb,   g_hb);
        cudaGetSymbolAddress((void**)&p_on,   g_on);
        cudaGetSymbolAddress((void**)&p_wa,   g_w12a);
        cudaGetSymbolAddress((void**)&p_wb,   g_w12b);
        cudaGetSymbolAddress((void**)&p_wpk,  g_wpk);
    }

    // edgeF smem: Bs1 + 2*Ab + Bs2 + As2 (uint2) + fs (float) + idx
    const int smeF = (128 * 84 + 2 * 128 * 12 + 128 * 20 + 128 * 20) * 8
                     + 64 * 132 * 4 + 1024;   // 186,368 B
    const int smg2 = 64 * 68 * 8 + 128;       // 34,944 B
    static bool attr_done = false;
    if (!attr_done) {
        cudaFuncSetAttribute(k_edgeF, cudaFuncAttributeMaxDynamicSharedMemorySize, smeF);
        cudaFuncSetAttribute(k_gemm2<true, false, false>,  cudaFuncAttributeMaxDynamicSharedMemorySize, smg2);
        cudaFuncSetAttribute(k_gemm2<false, true, false>,  cudaFuncAttributeMaxDynamicSharedMemorySize, smg2);
        cudaFuncSetAttribute(k_gemm2<true, false, true>,   cudaFuncAttributeMaxDynamicSharedMemorySize, smg2);
        cudaFuncSetAttribute(k_gemm2<false, true, true>,   cudaFuncAttributeMaxDynamicSharedMemorySize, smg2);
        cudaFuncSetAttribute(k_gemm2<false, false, false>, cudaFuncAttributeMaxDynamicSharedMemorySize, smg2);
        attr_done = true;
    }

    int NH_ = N_ * HH;
    int gZ = (NH_ + 255) / 256;
    int gB64 = (N_ + 63) / 64;
    const int WMAT = 128 * 68;

    // 0: pack everything   1: zero aggs   2: xh   3: k_edgeF (ncu capture target)
    k_prep_pack<<<269, 256>>>(f1_w1, f1_w2, f2_w1, f2_w2, lin_w,
                              conv1_rel_w, conv1_root_w, conv2_rel_w, conv2_root_w,
                              lin1_w, lin2_w, lincat_w, lins_w, final_w);
    k_zero2<<<gZ, 256>>>(NH_);
    k_gemm2<false, true, false><<<gB64, 256, smg2>>>(x, p_wpk + 0 * WMAT, nullptr, nullptr, lin_b, nullptr, p_xh, N_);
    k_edgeF<<<148, 512, smeF>>>(feature1, feature2, p_wa, p_wb, edge_index, p_xh, p_agg1, p_agg2, E_);

    // conv1 / lin1
    k_gemm2<true, false, false><<<gB64, 256, smg2>>>(p_agg1, p_wpk + 1 * WMAT, p_xh, p_wpk + 2 * WMAT, conv1_rel_b, nullptr, p_c, N_);
    k_gemm2<false, true, false><<<gB64, 256, smg2>>>(p_c, p_wpk + 5 * WMAT, nullptr, nullptr, lin1_b, nullptr, p_agg1, N_);
    // conv2 / lin2
    k_gemm2<true, false, false><<<gB64, 256, smg2>>>(p_agg2, p_wpk + 3 * WMAT, p_xh, p_wpk + 4 * WMAT, conv2_rel_b, nullptr, p_c, N_);
    k_gemm2<false, true, false><<<gB64, 256, smg2>>>(p_c, p_wpk + 6 * WMAT, nullptr, nullptr, lin2_b, nullptr, p_agg2, N_);

    // h = cat(h1,h2) @ lincat + b + xh
    k_gemm2<true, false, true><<<gB64, 256, smg2>>>(p_agg1, p_wpk + 7 * WMAT, p_agg2, p_wpk + 8 * WMAT, lincat_b, p_xh, p_ha, N_);

    // residual lins
    k_gemm2<false, true, true><<<gB64, 256, smg2>>>(p_ha, p_wpk + 9 * WMAT,  nullptr, nullptr, lins_b,          p_ha, p_hb, N_);
    k_gemm2<false, true, true><<<gB64, 256, smg2>>>(p_hb, p_wpk + 10 * WMAT, nullptr, nullptr, lins_b + HH,     p_hb, p_ha, N_);
    k_gemm2<false, true, true><<<gB64, 256, smg2>>>(p_ha, p_wpk + 11 * WMAT, nullptr, nullptr, lins_b + 2 * HH, p_ha, p_hb, N_);

    // fused GraphNorm (sorted batch)
    k_gnorm<<<GG, 128>>>(p_hb, batch, norm_ms, norm_w, norm_b, p_on, N_);

    // final projection
    k_gemm2<false, false, false><<<gB64, 256, smg2>>>(p_on, p_wpk + 12 * WMAT, nullptr, nullptr, final_b, nullptr, (float*)d_out, N_);
}

// round 13
// speedup vs baseline: 1.2130x; 1.0679x over previous
#include <cuda_runtime.h>
#include <cuda_bf16.h>
#include <cstdint>
#include <math.h>

#define HH 128
#define GG 512
#define MAXN 50000
#define NHH (MAXN * HH)

// ---------------- device scratch ----------------
__device__ float g_xh[NHH];
__device__ float g_agg1[NHH];
__device__ float g_agg2[NHH];
__device__ float g_hb[NHH];
__device__ float g_on[NHH];
__device__ uint2 g_w12a[128 * 84];       // packed split-bf16 W12 (feature1)
__device__ uint2 g_w12b[128 * 20];       // (feature2)
__device__ uint2 g_wpk[13 * 128 * 68];   // packed node weights

// ---------------- bf16 split helpers ----------------
__device__ __forceinline__ uint2 splitbf2p(float2 v) {
    __nv_bfloat162 h = __float22bfloat162_rn(v);
    float2 hv = __bfloat1622float2(h);
    __nv_bfloat162 l = __float22bfloat162_rn(make_float2(v.x - hv.x, v.y - hv.y));
    uint2 r;
    r.x = *reinterpret_cast<uint32_t*>(&h);
    r.y = *reinterpret_cast<uint32_t*>(&l);
    return r;
}

__device__ __forceinline__ void mma16(float* d, uint32_t a0, uint32_t a1, uint32_t a2,
                                      uint32_t a3, uint32_t b0, uint32_t b1) {
    asm volatile(
        "mma.sync.aligned.m16n8k16.row.col.f32.bf16.bf16.f32 "
        "{%0,%1,%2,%3}, {%4,%5,%6,%7}, {%8,%9}, {%0,%1,%2,%3};\n"
        : "+f"(d[0]), "+f"(d[1]), "+f"(d[2]), "+f"(d[3])
        : "r"(a0), "r"(a1), "r"(a2), "r"(a3), "r"(b0), "r"(b1));
}

__device__ __forceinline__ void mma3(float* d, const uint2& a0, const uint2& a1,
                                     const uint2& a2, const uint2& a3,
                                     uint32_t bh0, uint32_t bh1, uint32_t bl0, uint32_t bl1) {
    mma16(d, a0.x, a1.x, a2.x, a3.x, bh0, bh1);
    mma16(d, a0.x, a1.x, a2.x, a3.x, bl0, bl1);
    mma16(d, a0.y, a1.y, a2.y, a3.y, bh0, bh1);
}

// ---------------- prep: all weight packing in one kernel ----------------
__global__ void k_prep_pack(const float* __restrict__ f1_w1, const float* __restrict__ f1_w2,
                            const float* __restrict__ f2_w1, const float* __restrict__ f2_w2,
                            const float* __restrict__ lin_w, const float* __restrict__ c1r,
                            const float* __restrict__ c1t, const float* __restrict__ c2r,
                            const float* __restrict__ c2t, const float* __restrict__ l1w,
                            const float* __restrict__ l2w, const float* __restrict__ lcw,
                            const float* __restrict__ lsw, const float* __restrict__ fw) {
    int b = blockIdx.x, tid = threadIdx.x;
    if (b < 128) {
        if (tid < 84) {
            int k0 = 2 * tid, k1 = k0 + 1;
            float a0 = 0.f, a1 = 0.f;
            for (int m = 0; m < 64; m++) {
                float w2 = f1_w2[m * 128 + b];
                if (k0 < 147) a0 += f1_w1[k0 * 64 + m] * w2;
                if (k1 < 147) a1 += f1_w1[k1 * 64 + m] * w2;
            }
            g_w12a[b * 84 + tid] = splitbf2p(make_float2(a0, a1));
        }
    } else if (b < 256) {
        int n = b - 128;
        if (tid < 20) {
            int k0 = 2 * tid, k1 = k0 + 1;
            float a0 = 0.f, a1 = 0.f;
            for (int m = 0; m < 64; m++) {
                float w2 = f2_w2[m * 128 + n];
                if (k0 < 21) a0 += f2_w1[k0 * 64 + m] * w2;
                if (k1 < 21) a1 += f2_w1[k1 * 64 + m] * w2;
            }
            g_w12b[n * 20 + tid] = splitbf2p(make_float2(a0, a1));
        }
    } else {
        int m = b - 256;
        if (tid < 128 && m < 13) {
            const float* srcs[13] = {lin_w, c1r, c1t, c2r, c2t, l1w, l2w,
                                     lcw, lcw + HH * HH, lsw, lsw + HH * HH,
                                     lsw + 2 * HH * HH, fw};
            const float* W = srcs[m];
            uint2* dst = g_wpk + m * (128 * 68);
            for (int kp = 0; kp < 64; kp++) {
                float w0 = W[(2 * kp) * 128 + tid];
                float w1 = W[(2 * kp + 1) * 128 + tid];
                dst[tid * 68 + kp] = splitbf2p(make_float2(w0, w1));
            }
        }
    }
}

__global__ void k_zero2(int n) {
    int i = blockIdx.x * blockDim.x + threadIdx.x;
    if (i < n) { g_agg1[i] = 0.f; g_agg2[i] = 0.f; }
}

// ---------------- node GEMM: 256 thr, m64 tile (used for xh and final proj) ----------------
template <bool DUAL, bool SW, bool RES>
__global__ __launch_bounds__(256, 3) void k_gemm2(
    const float* __restrict__ A, const uint2* __restrict__ Wa,
    const float* __restrict__ B, const uint2* __restrict__ Wb,
    const float* __restrict__ bias, const float* __restrict__ R,
    float* __restrict__ out, int n) {
    constexpr int WW = 68;
    extern __shared__ uint2 shu[];
    uint2* As2 = shu;
    int tid = threadIdx.x, w = tid >> 5, lane = tid & 31, g = lane >> 2, t = lane & 3;
    int wg = w >> 2, wn = w & 3;
    int r0 = blockIdx.x * 64;

    float acc[2][4][4];
    #pragma unroll
    for (int mf = 0; mf < 2; mf++)
        #pragma unroll
        for (int nf = 0; nf < 4; nf++)
            #pragma unroll
            for (int i = 0; i < 4; i++) acc[mf][nf][i] = 0.f;

    const int NPASS = DUAL ? 2 : 1;
    for (int p = 0; p < NPASS; p++) {
        const float* Ain = p ? B : A;
        const uint2* Wp = p ? Wb : Wa;
        __syncthreads();
        for (int i = tid; i < 64 * 64; i += 256) {
            int r = i >> 6, kp = i & 63;
            int row = r0 + r;
            float2 v = (row < n) ? *(const float2*)(Ain + (size_t)row * 128 + 2 * kp)
                                 : make_float2(0.f, 0.f);
            As2[r * WW + kp] = splitbf2p(v);
        }
        __syncthreads();
        #pragma unroll
        for (int ks = 0; ks < 8; ks++) {
            int kp0 = ks * 8;
            uint32_t bh[4][2], bl[4][2];
            #pragma unroll
            for (int nf = 0; nf < 4; nf++) {
                int nn = wn * 32 + nf * 8 + g;
                uint2 b0 = __ldg(&Wp[nn * WW + kp0 + t]);
                uint2 b1 = __ldg(&Wp[nn * WW + kp0 + t + 4]);
                bh[nf][0] = b0.x; bl[nf][0] = b0.y;
                bh[nf][1] = b1.x; bl[nf][1] = b1.y;
            }
            #pragma unroll
            for (int mf = 0; mf < 2; mf++) {
                int r = wg * 32 + mf * 16 + g;
                uint2 a0 = As2[r * WW + kp0 + t];
                uint2 a1 = As2[(r + 8) * WW + kp0 + t];
                uint2 a2 = As2[r * WW + kp0 + t + 4];
                uint2 a3 = As2[(r + 8) * WW + kp0 + t + 4];
                #pragma unroll
                for (int nf = 0; nf < 4; nf++)
                    mma3(acc[mf][nf], a0, a1, a2, a3,
                         bh[nf][0], bh[nf][1], bl[nf][0], bl[nf][1]);
            }
        }
    }
    float2 bb[4];
    #pragma unroll
    for (int nf = 0; nf < 4; nf++) bb[nf] = *(const float2*)&bias[wn * 32 + nf * 8 + 2 * t];
    #pragma unroll
    for (int mf = 0; mf < 2; mf++) {
        #pragma unroll
        for (int half = 0; half < 2; half++) {
            int row = r0 + wg * 32 + mf * 16 + g + 8 * half;
            if (row < n) {
                #pragma unroll
                for (int nf = 0; nf < 4; nf++) {
                    int col = wn * 32 + nf * 8 + 2 * t;
                    float vx = acc[mf][nf][2 * half + 0] + bb[nf].x;
                    float vy = acc[mf][nf][2 * half + 1] + bb[nf].y;
                    if (SW) { vx = vx / (1.f + expf(-vx)); vy = vy / (1.f + expf(-vy)); }
                    if (RES) {
                        float2 rv = *(const float2*)&R[(size_t)row * 128 + col];
                        vx += rv.x; vy += rv.y;
                    }
                    *(float2*)&out[(size_t)row * 128 + col] = make_float2(vx, vy);
                }
            }
        }
    }
}

// ---------------- node megakernel: conv1..lins fused, intermediates in smem ----------------
__global__ __launch_bounds__(256, 2) void k_mega(
    const float* __restrict__ agg1, const float* __restrict__ agg2,
    const float* __restrict__ xh,
    const float* __restrict__ c1b, const float* __restrict__ l1b,
    const float* __restrict__ c2b, const float* __restrict__ l2b,
    const float* __restrict__ lcb, const float* __restrict__ lsb,
    float* __restrict__ out, int n) {
    constexpr int WW = 68;
    extern __shared__ uint2 shu[];
    uint2* As2 = shu;                       // [64][68]
    float* U = (float*)(shu + 64 * WW);     // [64][132]
    float* V = U + 64 * 132;                // [64][132]
    int tid = threadIdx.x, w = tid >> 5, lane = tid & 31, g = lane >> 2, t = lane & 3;
    int wg = w >> 2, wn = w & 3;
    int r0 = blockIdx.x * 64;

    float acc[2][4][4];
    auto zacc = [&]() {
        #pragma unroll
        for (int mf = 0; mf < 2; mf++)
            #pragma unroll
            for (int nf = 0; nf < 4; nf++)
                #pragma unroll
                for (int i = 0; i < 4; i++) acc[mf][nf][i] = 0.f;
    };
    auto stageG = [&](const float* Ain) {
        __syncthreads();
        for (int i = tid; i < 64 * 64; i += 256) {
            int r = i >> 6, kp = i & 63;
            int row = r0 + r;
            float2 v = (row < n) ? *(const float2*)(Ain + (size_t)row * 128 + 2 * kp)
                                 : make_float2(0.f, 0.f);
            As2[r * WW + kp] = splitbf2p(v);
        }
        __syncthreads();
    };
    auto stageS = [&](const float* S) {
        __syncthreads();
        for (int i = tid; i < 64 * 64; i += 256) {
            int r = i >> 6, kp = i & 63;
            As2[r * WW + kp] = splitbf2p(*(const float2*)&S[r * 132 + 2 * kp]);
        }
        __syncthreads();
    };
    auto mmaW = [&](const uint2* Wp) {
        #pragma unroll
        for (int ks = 0; ks < 8; ks++) {
            int kp0 = ks * 8;
            uint32_t bh[4][2], bl[4][2];
            #pragma unroll
            for (int nf = 0; nf < 4; nf++) {
                int nn = wn * 32 + nf * 8 + g;
                uint2 b0 = __ldg(&Wp[nn * WW + kp0 + t]);
                uint2 b1 = __ldg(&Wp[nn * WW + kp0 + t + 4]);
                bh[nf][0] = b0.x; bl[nf][0] = b0.y;
                bh[nf][1] = b1.x; bl[nf][1] = b1.y;
            }
            #pragma unroll
            for (int mf = 0; mf < 2; mf++) {
                int r = wg * 32 + mf * 16 + g;
                uint2 a0 = As2[r * WW + kp0 + t];
                uint2 a1 = As2[(r + 8) * WW + kp0 + t];
                uint2 a2 = As2[r * WW + kp0 + t + 4];
                uint2 a3 = As2[(r + 8) * WW + kp0 + t + 4];
                #pragma unroll
                for (int nf = 0; nf < 4; nf++)
                    mma3(acc[mf][nf], a0, a1, a2, a3,
                         bh[nf][0], bh[nf][1], bl[nf][0], bl[nf][1]);
            }
        }
    };
    // epi: SW swish; resid: 0 none, 1 smem Rs, 2 global xh. dstS != nullptr -> smem out, else global out.
    auto epi = [&](float* dstS, float* dstG, const float* bias, bool SW,
                   int rmode, const float* Rs) {
        float2 bb[4];
        #pragma unroll
        for (int nf = 0; nf < 4; nf++) bb[nf] = *(const float2*)&bias[wn * 32 + nf * 8 + 2 * t];
        #pragma unroll
        for (int mf = 0; mf < 2; mf++) {
            #pragma unroll
            for (int half = 0; half < 2; half++) {
                int rl = wg * 32 + mf * 16 + g + 8 * half;
                int row = r0 + rl;
                #pragma unroll
                for (int nf = 0; nf < 4; nf++) {
                    int col = wn * 32 + nf * 8 + 2 * t;
                    float vx = acc[mf][nf][2 * half + 0] + bb[nf].x;
                    float vy = acc[mf][nf][2 * half + 1] + bb[nf].y;
                    if (SW) { vx = vx / (1.f + expf(-vx)); vy = vy / (1.f + expf(-vy)); }
                    if (rmode == 1) {
                        float2 rv = *(const float2*)&Rs[rl * 132 + col];
                        vx += rv.x; vy += rv.y;
                    } else if (rmode == 2 && row < n) {
                        float2 rv = *(const float2*)&xh[(size_t)row * 128 + col];
                        vx += rv.x; vy += rv.y;
                    }
                    if (dstS) {
                        *(float2*)&dstS[rl * 132 + col] = make_float2(vx, vy);
                    } else if (row < n) {
                        *(float2*)&dstG[(size_t)row * 128 + col] = make_float2(vx, vy);
                    }
                }
            }
        }
    };

    // c1 = agg1@W1 + xh@W2 + c1b -> U
    zacc(); stageG(agg1); mmaW(g_wpk + 1 * 128 * WW);
    stageG(xh); mmaW(g_wpk + 2 * 128 * WW);
    epi(U, nullptr, c1b, false, 0, nullptr);
    // h1 = swish(c1@Wl1 + l1b) -> U
    zacc(); stageS(U); mmaW(g_wpk + 5 * 128 * WW);
    epi(U, nullptr, l1b, true, 0, nullptr);
    // c2 -> V
    zacc(); stageG(agg2); mmaW(g_wpk + 3 * 128 * WW);
    stageG(xh); mmaW(g_wpk + 4 * 128 * WW);
    epi(V, nullptr, c2b, false, 0, nullptr);
    // h2 = swish(c2@Wl2 + l2b) -> V
    zacc(); stageS(V); mmaW(g_wpk + 6 * 128 * WW);
    epi(V, nullptr, l2b, true, 0, nullptr);
    // ha = h1@Wlc1 + h2@Wlc2 + lcb + xh -> U
    zacc(); stageS(U); mmaW(g_wpk + 7 * 128 * WW);
    stageS(V); mmaW(g_wpk + 8 * 128 * WW);
    epi(U, nullptr, lcb, false, 2, nullptr);
    // lins 0: V = swish(U@W+b0) + U
    zacc(); stageS(U); mmaW(g_wpk + 9 * 128 * WW);
    epi(V, nullptr, lsb, true, 1, U);
    // lins 1: U = swish(V@W+b1) + V
    zacc(); stageS(V); mmaW(g_wpk + 10 * 128 * WW);
    epi(U, nullptr, lsb + HH, true, 1, V);
    // lins 2: out = swish(U@W+b2) + U  (global)
    zacc(); stageS(U); mmaW(g_wpk + 11 * 128 * WW);
    epi(nullptr, out, lsb + 2 * HH, true, 1, U);
}

// ---------------- fused edge GEMM: f1 (band-synced pipeline) + f2 ----------------
__global__ __launch_bounds__(512, 1) void k_edgeF(
    const float* __restrict__ feat1, const float* __restrict__ feat2,
    const uint2* __restrict__ w12a, const uint2* __restrict__ w12b,
    const int* __restrict__ ei, const float* __restrict__ xh,
    float* __restrict__ agg1, float* __restrict__ agg2, int E) {
    constexpr int WP = 84;
    constexpr int AW = 12;
    constexpr int WP2 = 20;
    extern __shared__ uint2 shu[];
    uint2* Bs1 = shu;                         // [128][84]
    uint2* Ab0 = Bs1 + 128 * WP;              // [128][12]
    uint2* Ab1 = Ab0 + 128 * AW;              // [128][12]
    uint2* Bs2 = Ab1 + 128 * AW;              // [128][20]
    uint2* As2 = Bs2 + 128 * WP2;             // [128][20]
    float* fs  = (float*)(As2 + 128 * WP2);   // [64][132]
    int* srcs = (int*)(fs + 64 * 132);
    int* dsts = srcs + 128;

    int tid = threadIdx.x, w = tid >> 5, lane = tid & 31, g = lane >> 2, t = lane & 3;
    int wg = w >> 2, wn = w & 3;
    int bt = tid & 127;                 // position within band
    int brow = wg * 32 + (bt >> 2);     // band-local staging row (0..127 across bands)
    int bt4 = bt & 3;

    for (int i = tid; i < 128 * WP; i += 512) Bs1[i] = w12a[i];
    for (int i = tid; i < 128 * WP2; i += 512) Bs2[i] = w12b[i];

    int ntiles = (E + 127) >> 7;

    float acc[2][4][4];
    auto epilogue = [&](int tile, float* aggp) {
        #pragma unroll
        for (int h = 0; h < 2; h++) {
            __syncthreads();
            if ((wg >> 1) == h) {
                int rbase = (wg & 1) * 32;
                #pragma unroll
                for (int mf = 0; mf < 2; mf++) {
                    int rb = rbase + mf * 16 + g;
                    #pragma unroll
                    for (int nf = 0; nf < 4; nf++) {
                        int col = wn * 32 + nf * 8 + 2 * t;
                        *(float2*)&fs[rb * 132 + col] =
                            make_float2(acc[mf][nf][0], acc[mf][nf][1]);
                        *(float2*)&fs[(rb + 8) * 132 + col] =
                            make_float2(acc[mf][nf][2], acc[mf][nf][3]);
                    }
                }
            }
            __syncthreads();
            int rl = tid >> 3, q = tid & 7;
            int ed = tile * 128 + h * 64 + rl;
            if (ed < E) {
                int s = srcs[h * 64 + rl], d = dsts[h * 64 + rl];
                const float4* xr = (const float4*)(xh + (size_t)s * 128);
                float4* ar = (float4*)(aggp + (size_t)d * 128);
                #pragma unroll
                for (int i = 0; i < 4; i++) {
                    int c4 = q + 8 * i;
                    float4 f = *(float4*)&fs[rl * 132 + 4 * c4];
                    float4 xv = xr[c4];
                    atomicAdd(ar + c4,
                              make_float4(f.x * xv.x, f.y * xv.y, f.z * xv.z, f.w * xv.w));
                }
            }
        }
    };

    float lf[4];
    // prologue: stage f1 chunk0 of first tile (band-local mapping)
    if ((int)blockIdx.x < ntiles) {
        int ed = blockIdx.x * 128 + brow;
        const float* fr = feat1 + (size_t)ed * 147 + 4 * bt4;
        #pragma unroll
        for (int j = 0; j < 4; j++) lf[j] = (ed < E) ? fr[j] : 0.f;
        uint2 u0 = splitbf2p(make_float2(lf[0], lf[1]));
        uint2 u1 = splitbf2p(make_float2(lf[2], lf[3]));
        *(uint4*)&Ab0[brow * AW + 2 * bt4] = make_uint4(u0.x, u0.y, u1.x, u1.y);
    }
    __syncthreads();

    for (int tile = blockIdx.x; tile < ntiles; tile += gridDim.x) {
        #pragma unroll
        for (int mf = 0; mf < 2; mf++)
            #pragma unroll
            for (int nf = 0; nf < 4; nf++)
                #pragma unroll
                for (int i = 0; i < 4; i++) acc[mf][nf][i] = 0.f;

        if (tid < 128) {
            int ed = tile * 128 + tid;
            srcs[tid] = (ed < E) ? ei[ed] : 0;
            dsts[tid] = (ed < E) ? ei[(size_t)E + ed] : 0;
        }
        // stage f2 features early (consumed after epilogue1 block syncs)
        for (int i = tid; i < 128 * WP2; i += 512) {
            int r = i / WP2, kp = i - r * WP2;
            int ed = tile * 128 + r;
            int k0 = 2 * kp;
            float v0 = 0.f, v1 = 0.f;
            if (ed < E && k0 < 21) {
                const float* fr = feat2 + (size_t)ed * 21;
                v0 = fr[k0];
                if (k0 + 1 < 21) v1 = fr[k0 + 1];
            }
            As2[r * WP2 + kp] = splitbf2p(make_float2(v0, v1));
        }

        // ---- f1: 10 chunks, band-local sync ----
        for (int c = 0; c < 10; c++) {
            uint2* cur = (c & 1) ? Ab1 : Ab0;
            uint2* nxt = (c & 1) ? Ab0 : Ab1;
            int nt = tile, nc = c + 1;
            if (nc == 10) { nt = tile + gridDim.x; nc = 0; }
            bool dl = (nt < ntiles);
            if (dl) {
                int ed = nt * 128 + brow;
                int kb = 16 * nc + 4 * bt4;
                const float* fr = feat1 + (size_t)ed * 147 + kb;
                #pragma unroll
                for (int j = 0; j < 4; j++)
                    lf[j] = (ed < E && (kb + j) < 147) ? fr[j] : 0.f;
            }
            {
                int kbp = 8 * c;
                uint32_t bh[4][2], bl[4][2];
                #pragma unroll
                for (int nf = 0; nf < 4; nf++) {
                    int nn = wn * 32 + nf * 8 + g;
                    uint2 b0 = Bs1[nn * WP + kbp + t];
                    uint2 b1 = Bs1[nn * WP + kbp + t + 4];
                    bh[nf][0] = b0.x; bl[nf][0] = b0.y;
                    bh[nf][1] = b1.x; bl[nf][1] = b1.y;
                }
                #pragma unroll
                for (int mf = 0; mf < 2; mf++) {
                    int rr = wg * 32 + mf * 16 + g;
                    uint2 a0 = cur[rr * AW + t];
                    uint2 a1 = cur[(rr + 8) * AW + t];
                    uint2 a2 = cur[rr * AW + t + 4];
                    uint2 a3 = cur[(rr + 8) * AW + t + 4];
                    #pragma unroll
                    for (int nf = 0; nf < 4; nf++)
                        mma3(acc[mf][nf], a0, a1, a2, a3,
                             bh[nf][0], bh[nf][1], bl[nf][0], bl[nf][1]);
                }
            }
            if (dl) {
                uint2 u0 = splitbf2p(make_float2(lf[0], lf[1]));
                uint2 u1 = splitbf2p(make_float2(lf[2], lf[3]));
                *(uint4*)&nxt[brow * AW + 2 * bt4] = make_uint4(u0.x, u0.y, u1.x, u1.y);
            }
            // band-local barrier: 4 warps sharing this 32-row band
            asm volatile("bar.sync %0, %1;" :: "r"(wg + 1), "r"(128) : "memory");
        }
        epilogue(tile, agg1);

        // ---- f2: 2 k-steps ----
        #pragma unroll
        for (int mf = 0; mf < 2; mf++)
            #pragma unroll
            for (int nf = 0; nf < 4; nf++)
                #pragma unroll
                for (int i = 0; i < 4; i++) acc[mf][nf][i] = 0.f;
        #pragma unroll
        for (int ks = 0; ks < 2; ks++) {
            int kp0 = ks * 8;
            uint32_t bh[4][2], bl[4][2];
            #pragma unroll
            for (int nf = 0; nf < 4; nf++) {
                int nn = wn * 32 + nf * 8 + g;
                uint2 b0 = Bs2[nn * WP2 + kp0 + t];
                uint2 b1 = Bs2[nn * WP2 + kp0 + t + 4];
                bh[nf][0] = b0.x; bl[nf][0] = b0.y;
                bh[nf][1] = b1.x; bl[nf][1] = b1.y;
            }
            #pragma unroll
            for (int mf = 0; mf < 2; mf++) {
                int rr = wg * 32 + mf * 16 + g;
                uint2 a0 = As2[rr * WP2 + kp0 + t];
                uint2 a1 = As2[(rr + 8) * WP2 + kp0 + t];
                uint2 a2 = As2[rr * WP2 + kp0 + t + 4];
                uint2 a3 = As2[(rr + 8) * WP2 + kp0 + t + 4];
                #pragma unroll
                for (int nf = 0; nf < 4; nf++)
                    mma3(acc[mf][nf], a0, a1, a2, a3,
                         bh[nf][0], bh[nf][1], bl[nf][0], bl[nf][1]);
            }
        }
        epilogue(tile, agg2);
        __syncthreads();
    }
}

// ---------------- fused GraphNorm (batch sorted: block per graph) ----------------
__global__ __launch_bounds__(128) void k_gnorm(
    const float* __restrict__ h, const int* __restrict__ batch,
    const float* __restrict__ ms, const float* __restrict__ w,
    const float* __restrict__ b, float* __restrict__ out, int n) {
    int g = blockIdx.x;
    int c = threadIdx.x;
    int lo = 0, hi = n;
    while (lo < hi) { int mid = (lo + hi) >> 1; if (batch[mid] < g) lo = mid + 1; else hi = mid; }
    int start = lo;
    hi = n;
    while (lo < hi) { int mid = (lo + hi) >> 1; if (batch[mid] < g + 1) lo = mid + 1; else hi = mid; }
    int end = lo;
    int cnt = end - start;
    if (cnt <= 0) return;
    float fc = (float)cnt;

    float s0 = 0.f, s1 = 0.f, s2 = 0.f, s3 = 0.f;
    int r = start;
    for (; r + 3 < end; r += 4) {
        s0 += h[(size_t)r * 128 + c];
        s1 += h[(size_t)(r + 1) * 128 + c];
        s2 += h[(size_t)(r + 2) * 128 + c];
        s3 += h[(size_t)(r + 3) * 128 + c];
    }
    for (; r < end; r++) s0 += h[(size_t)r * 128 + c];
    float mean = (s0 + s1 + s2 + s3) / fc;
    float sub = mean * ms[c];

    float v0 = 0.f, v1 = 0.f;
    for (r = start; r + 1 < end; r += 2) {
        float o0 = h[(size_t)r * 128 + c] - sub;
        float o1 = h[(size_t)(r + 1) * 128 + c] - sub;
        out[(size_t)r * 128 + c] = o0;
        out[(size_t)(r + 1) * 128 + c] = o1;
        v0 += o0 * o0; v1 += o1 * o1;
    }
    for (; r < end; r++) {
        float o = h[(size_t)r * 128 + c] - sub;
        out[(size_t)r * 128 + c] = o;
        v0 += o * o;
    }
    float inv = rsqrtf((v0 + v1) / fc + 1e-5f);
    float wc = w[c] * inv, bc = b[c];

    for (r = start; r < end; r++) {
        size_t idx = (size_t)r * 128 + c;
        out[idx] = wc * out[idx] + bc;
    }
}

// ---------------- launch ----------------
extern "C" void kernel_launch(void* const* d_in, const int* in_sizes, int n_in,
                              void* d_out, int out_size) {
    const float* x          = (const float*)d_in[0];
    const float* feature1   = (const float*)d_in[1];
    const float* feature2   = (const float*)d_in[2];
    const int*   edge_index = (const int*)d_in[3];
    const int*   batch      = (const int*)d_in[4];
    const float* lin_w        = (const float*)d_in[5];
    const float* lin_b        = (const float*)d_in[6];
    const float* f1_w1        = (const float*)d_in[7];
    const float* f1_w2        = (const float*)d_in[8];
    const float* f2_w1        = (const float*)d_in[9];
    const float* f2_w2        = (const float*)d_in[10];
    const float* conv1_rel_w  = (const float*)d_in[11];
    const float* conv1_rel_b  = (const float*)d_in[12];
    const float* conv1_root_w = (const float*)d_in[13];
    const float* conv2_rel_w  = (const float*)d_in[14];
    const float* conv2_rel_b  = (const float*)d_in[15];
    const float* conv2_root_w = (const float*)d_in[16];
    const float* lin1_w       = (const float*)d_in[17];
    const float* lin1_b       = (const float*)d_in[18];
    const float* lin2_w       = (const float*)d_in[19];
    const float* lin2_b       = (const float*)d_in[20];
    const float* lincat_w     = (const float*)d_in[21];
    const float* lincat_b     = (const float*)d_in[22];
    const float* norm_w       = (const float*)d_in[23];
    const float* norm_b       = (const float*)d_in[24];
    const float* norm_ms      = (const float*)d_in[25];
    const float* lins_w       = (const float*)d_in[26];
    const float* lins_b       = (const float*)d_in[27];
    const float* final_w      = (const float*)d_in[28];
    const float* final_b      = (const float*)d_in[29];

    int N_ = in_sizes[0] / HH;
    int E_ = in_sizes[3] / 2;

    static float *p_xh = nullptr, *p_agg1, *p_agg2, *p_hb, *p_on;
    static uint2 *p_wa, *p_wb, *p_wpk;
    if (!p_xh) {
        cudaGetSymbolAddress((void**)&p_xh,   g_xh);
        cudaGetSymbolAddress((void**)&p_agg1, g_agg1);
        cudaGetSymbolAddress((void**)&p_agg2, g_agg2);
        cudaGetSymbolAddress((void**)&p_hb,   g_hb);
        cudaGetSymbolAddress((void**)&p_on,   g_on);
        cudaGetSymbolAddress((void**)&p_wa,   g_w12a);
        cudaGetSymbolAddress((void**)&p_wb,   g_w12b);
        cudaGetSymbolAddress((void**)&p_wpk,  g_wpk);
    }

    const int smeF = (128 * 84 + 2 * 128 * 12 + 128 * 20 + 128 * 20) * 8
                     + 64 * 132 * 4 + 1024;                        // 186,368 B
    const int smg2 = 64 * 68 * 8 + 128;                            // 34,944 B
    const int smM  = 64 * 68 * 8 + 2 * 64 * 132 * 4 + 256;         // 102,656 B
    static bool attr_done = false;
    if (!attr_done) {
        cudaFuncSetAttribute(k_edgeF, cudaFuncAttributeMaxDynamicSharedMemorySize, smeF);
        cudaFuncSetAttribute(k_mega,  cudaFuncAttributeMaxDynamicSharedMemorySize, smM);
        cudaFuncSetAttribute(k_gemm2<false, true, false>,  cudaFuncAttributeMaxDynamicSharedMemorySize, smg2);
        cudaFuncSetAttribute(k_gemm2<false, false, false>, cudaFuncAttributeMaxDynamicSharedMemorySize, smg2);
        attr_done = true;
    }

    int NH_ = N_ * HH;
    int gZ = (NH_ + 255) / 256;
    int gB64 = (N_ + 63) / 64;
    const int WMAT = 128 * 68;

    // 0 prep, 1 zero, 2 xh, 3 edgeF(capture), 4 mega, 5 gnorm, 6 final
    k_prep_pack<<<269, 256>>>(f1_w1, f1_w2, f2_w1, f2_w2, lin_w,
                              conv1_rel_w, conv1_root_w, conv2_rel_w, conv2_root_w,
                              lin1_w, lin2_w, lincat_w, lins_w, final_w);
    k_zero2<<<gZ, 256>>>(NH_);
    k_gemm2<false, true, false><<<gB64, 256, smg2>>>(x, p_wpk + 0 * WMAT, nullptr, nullptr, lin_b, nullptr, p_xh, N_);
    k_edgeF<<<148, 512, smeF>>>(feature1, feature2, p_wa, p_wb, edge_index, p_xh, p_agg1, p_agg2, E_);
    k_mega<<<gB64, 256, smM>>>(p_agg1, p_agg2, p_xh,
                               conv1_rel_b, lin1_b, conv2_rel_b, lin2_b,
                               lincat_b, lins_b, p_hb, N_);
    k_gnorm<<<GG, 128>>>(p_hb, batch, norm_ms, norm_w, norm_b, p_on, N_);
    k_gemm2<false, false, false><<<gB64, 256, smg2>>>(p_on, p_wpk + 12 * WMAT, nullptr, nullptr, final_b, nullptr, (float*)d_out, N_);
}